// round 12
// baseline (speedup 1.0000x reference)
#include <cuda_runtime.h>
#include <cstdint>

#define CC 1024

// ---- device scratch ----
__device__ float g_L[8 * 2048 * CC];
__device__ float g_S[8 * 2048 * CC];
__device__ float g_vbuf[8 * 1024 * CC];
__device__ float g_Amul[8 * 1024 * CC];
__device__ float g_Z[8192 * CC];
__device__ float g_ow1[CC * CC];
__device__ float g_ow2[CC * CC];
__device__ float g_Utmp[CC * CC];
__device__ float g_probe1[CC];
__device__ float g_probe2[CC];
__device__ float g_rowsq[CC];
__device__ float g_ss;

__device__ __forceinline__ uint32_t smem_to_u32(const void* p) {
    uint32_t a;
    asm("{ .reg .u64 t; cvta.to.shared.u64 t, %1; cvt.u32.u64 %0, t; }" : "=r"(a) : "l"(p));
    return a;
}

__device__ __forceinline__ void split1(uint32_t raw, uint32_t& h, uint32_t& l) {
    h = raw & 0xffffe000u;
    float lf = __uint_as_float(raw) - __uint_as_float(h);
    l = __float_as_uint(lf) & 0xffffe000u;
}

__device__ __forceinline__ void mma8(float* c, const uint32_t* a, uint32_t b0, uint32_t b1) {
    asm volatile("mma.sync.aligned.m16n8k8.row.col.f32.tf32.tf32.f32 "
                 "{%0,%1,%2,%3}, {%4,%5,%6,%7}, {%8,%9}, {%0,%1,%2,%3};"
                 : "+f"(c[0]), "+f"(c[1]), "+f"(c[2]), "+f"(c[3])
                 : "r"(a[0]), "r"(a[1]), "r"(a[2]), "r"(a[3]), "r"(b0), "r"(b1));
}

__device__ __forceinline__ void cp16(uint32_t dst, const void* src) {
    asm volatile("cp.async.ca.shared.global [%0], [%1], 16;" :: "r"(dst), "l"(src));
}
#define CP_COMMIT() asm volatile("cp.async.commit_group;")
#define CP_WAIT1()  asm volatile("cp.async.wait_group 1;")
#define CP_WAIT0()  asm volatile("cp.async.wait_group 0;")

// SMEM: 2 stages x 32KB. Per stage (u32 idx):
//   A word (row,k)  at ((row>>4)*4 + (k>>3))*128 + (((row>>3)&1) + 2*((k>>2)&1))*32 + (row&7)*4 + (k&3)
//   B word (n,k) at 4096 + ((n>>3)*4 + (k>>3))*64 + ((k>>2)&1)*32 + (n&7)*4 + (k&3)
#define TG_SMEM 65536

// ---- hybrid tensor(3xTF32, k 0..23) + scalar-FFMA(fp32 exact, k 24..31) GEMM ----
// D[M x 1024]; k-tiles 0..31 use (A1,B1), 32..63 use (A2,B2) when nkt=64.
// A/O rows via (base,n,off,stride,cnt) map. B rows are output dims [N,K].
// blockIdx.z = kz (split-K): k-tiles [kz*per, kz*per+per) -> partial at O + kz*M*1024.
__global__ __launch_bounds__(256, 2)
void tgemm_kernel(int M, int nkt, int ks,
                  const float* __restrict__ A1, int a1n, int a1off, int a1str, int a1cnt,
                  const float* __restrict__ B1,
                  const float* __restrict__ A2, int a2n, int a2off, int a2str, int a2cnt,
                  const float* __restrict__ B2,
                  float* __restrict__ O, int on, int ooff, int ostr, int ocnt) {
    extern __shared__ uint32_t sm[];
    const uint32_t smb = smem_to_u32(sm);
    const int tid = threadIdx.x;
    const int wid = tid >> 5, lane = tid & 31;
    const int wm = wid >> 2, wn = wid & 3;
    const int g = lane >> 2, t4 = lane & 3;
    const int bn = blockIdx.x * 128, bm = blockIdx.y * 128;
    const int kz = blockIdx.z;

    const int rr = tid & 127, kh2 = tid >> 7;
    int gr = bm + rr; if (gr > M - 1) gr = M - 1;
    const float* ap1 = A1 + ((size_t)(gr / a1cnt) * a1n + a1off + (size_t)(gr % a1cnt) * a1str) * 1024;
    const float* ap2 = A2 + ((size_t)(gr / a2cnt) * a2n + a2off + (size_t)(gr % a2cnt) * a2str) * 1024;
    const float* bp1 = B1 + (size_t)(bn + rr) * 1024;
    const float* bp2 = B2 + (size_t)(bn + rr) * 1024;

    uint32_t adst[4], bdst[4];
    int asrc[4];
    #pragma unroll
    for (int f = 0; f < 4; f++) {
        int kq = kh2 * 4 + f, kt = kq >> 1, kh = kq & 1;
        adst[f] = ((((rr >> 4) * 4 + kt) * 128 + (((rr >> 3) & 1) + 2 * kh) * 32 + (rr & 7) * 4)) * 4u;
        bdst[f] = ((4096 + ((rr >> 3) * 4 + kt) * 64 + kh * 32 + (rr & 7) * 4)) * 4u;
        asrc[f] = kq * 4;
    }

    float acc[4][4][4];
    #pragma unroll
    for (int i = 0; i < 4; i++)
        #pragma unroll
        for (int j = 0; j < 4; j++)
            #pragma unroll
            for (int q = 0; q < 4; q++) acc[i][j][q] = 0.f;

    const int per = nkt / ks;
    const int c0 = kz * per, c1 = c0 + per;

    auto issue = [&](int c) {
        const float* ap = (c >= 32) ? ap2 : ap1;
        const float* bp = (c >= 32) ? bp2 : bp1;
        int ko = (c & 31) * 32;
        uint32_t st = smb + (uint32_t)(c & 1) * 32768u;
        #pragma unroll
        for (int f = 0; f < 4; f++) {
            cp16(st + adst[f], ap + ko + asrc[f]);
            cp16(st + bdst[f], bp + ko + asrc[f]);
        }
        CP_COMMIT();
    };

    issue(c0);
    if (per > 1) issue(c0 + 1);

    // scalar-path smem bases (u32 index, stage-relative):
    //   A(row,k): row = wm*64 + mt*16 + g + 8h, k in 24..31 -> k>>3 = 3
    //   idx = (wm*4+mt)*512 + 3*128 + (h + 2*kh)*32 + g*4 + (k&3)
    //   B(n,k):   n = wn*32 + nt*8 + 2*t4 + d
    //   idx = 4096 + ((wn*4+nt)*4 + 3)*64 + kh*32 + (2*t4+d)*4 + (k&3)
    const int sA0 = wm * 2048 + 384 + g * 4;
    const int sB0 = 4096 + wn * 1024 + 192 + t4 * 8;

    for (int c = c0; c < c1; c++) {
        if (c + 1 < c1) { CP_WAIT1(); } else { CP_WAIT0(); }
        __syncthreads();
        const int st32 = (c & 1) * 8192;
        #pragma unroll
        for (int ks_ = 0; ks_ < 3; ks_++) {
            // ---- tensor chunk (k = ks_*8 .. ks_*8+7) ----
            uint32_t ah[4][4], al[4][4];
            #pragma unroll
            for (int mt = 0; mt < 4; mt++) {
                int base = st32 + ((wm * 4 + mt) * 4 + ks_) * 128 + lane;
                #pragma unroll
                for (int r = 0; r < 4; r++) split1(sm[base + r * 32], ah[mt][r], al[mt][r]);
            }
            #pragma unroll
            for (int nt = 0; nt < 4; nt++) {
                int bb = st32 + 4096 + ((wn * 4 + nt) * 4 + ks_) * 64 + lane;
                uint32_t b0h, b0l, b1h, b1l;
                split1(sm[bb], b0h, b0l);
                split1(sm[bb + 32], b1h, b1l);
                #pragma unroll
                for (int mt = 0; mt < 4; mt++) {
                    mma8(acc[mt][nt], ah[mt], b0h, b1h);
                    mma8(acc[mt][nt], ah[mt], b0l, b1l);
                    mma8(acc[mt][nt], al[mt], b0h, b1h);
                }
            }
            // ---- scalar chunk: k = 24..26 / 27..29 / 30..31 (FMA pipe, exact fp32) ----
            const int kbeg = 24 + ks_ * 3;
            const int kend = (ks_ == 2) ? 32 : kbeg + 3;
            #pragma unroll
            for (int kk = kbeg; kk < kend; kk++) {
                const int kh = (kk >> 2) & 1, kq3 = kk & 3;
                float av[8], bv[8];
                #pragma unroll
                for (int mt = 0; mt < 4; mt++) {
                    av[mt * 2 + 0] = __uint_as_float(sm[st32 + sA0 + mt * 512 + kh * 64 + kq3]);
                    av[mt * 2 + 1] = __uint_as_float(sm[st32 + sA0 + mt * 512 + kh * 64 + 32 + kq3]);
                }
                #pragma unroll
                for (int nt = 0; nt < 4; nt++) {
                    bv[nt * 2 + 0] = __uint_as_float(sm[st32 + sB0 + nt * 256 + kh * 32 + kq3]);
                    bv[nt * 2 + 1] = __uint_as_float(sm[st32 + sB0 + nt * 256 + kh * 32 + 4 + kq3]);
                }
                #pragma unroll
                for (int mt = 0; mt < 4; mt++)
                    #pragma unroll
                    for (int nt = 0; nt < 4; nt++) {
                        acc[mt][nt][0] = fmaf(av[mt * 2 + 0], bv[nt * 2 + 0], acc[mt][nt][0]);
                        acc[mt][nt][1] = fmaf(av[mt * 2 + 0], bv[nt * 2 + 1], acc[mt][nt][1]);
                        acc[mt][nt][2] = fmaf(av[mt * 2 + 1], bv[nt * 2 + 0], acc[mt][nt][2]);
                        acc[mt][nt][3] = fmaf(av[mt * 2 + 1], bv[nt * 2 + 1], acc[mt][nt][3]);
                    }
            }
        }
        __syncthreads();
        if (c + 2 < c1) issue(c + 2);
    }

    O += (size_t)kz * M * 1024;

    #pragma unroll
    for (int mt = 0; mt < 4; mt++) {
        int r0 = bm + wm * 64 + mt * 16 + g;
        #pragma unroll
        for (int half = 0; half < 2; half++) {
            int r = r0 + half * 8;
            if (r < M) {
                float* orow = O + ((size_t)(r / ocnt) * on + ooff + (size_t)(r % ocnt) * ostr) * 1024
                              + bn + wn * 32;
                #pragma unroll
                for (int nt = 0; nt < 4; nt++) {
                    float2 v = half ? make_float2(acc[mt][nt][2], acc[mt][nt][3])
                                    : make_float2(acc[mt][nt][0], acc[mt][nt][1]);
                    *(float2*)(orow + nt * 8 + t4 * 2) = v;
                }
            }
        }
    }
}

// ---- threefry2x32 (exact JAX, partitionable layout) -> normal probes ----
__device__ __forceinline__ unsigned rotl32(unsigned x, int d) { return (x << d) | (x >> (32 - d)); }

__device__ void threefry2x32(unsigned k0, unsigned k1, unsigned x0, unsigned x1,
                             unsigned* o0, unsigned* o1) {
    unsigned ks[3] = {k0, k1, k0 ^ k1 ^ 0x1BD11BDAu};
    const int rot0[4] = {13, 15, 26, 6};
    const int rot1[4] = {17, 29, 16, 24};
    x0 += ks[0]; x1 += ks[1];
    #pragma unroll
    for (int g = 0; g < 5; g++) {
        if ((g & 1) == 0) {
            #pragma unroll
            for (int j = 0; j < 4; j++) { x0 += x1; x1 = rotl32(x1, rot0[j]); x1 ^= x0; }
        } else {
            #pragma unroll
            for (int j = 0; j < 4; j++) { x0 += x1; x1 = rotl32(x1, rot1[j]); x1 ^= x0; }
        }
        x0 += ks[(g + 1) % 3];
        x1 += ks[(g + 2) % 3] + (unsigned)(g + 1);
    }
    *o0 = x0; *o1 = x1;
}

__device__ float erfinv_f32(float x) {  // XLA ErfInv32 (Giles)
    float w = -log1pf(-x * x), p;
    if (w < 5.0f) {
        w -= 2.5f;
        p = 2.81022636e-08f;
        p = fmaf(p, w, 3.43273939e-07f);  p = fmaf(p, w, -3.5233877e-06f);
        p = fmaf(p, w, -4.39150654e-06f); p = fmaf(p, w, 0.00021858087f);
        p = fmaf(p, w, -0.00125372503f);  p = fmaf(p, w, -0.00417768164f);
        p = fmaf(p, w, 0.246640727f);     p = fmaf(p, w, 1.50140941f);
    } else {
        w = sqrtf(w) - 3.0f;
        p = -0.000200214257f;
        p = fmaf(p, w, 0.000100950558f);  p = fmaf(p, w, 0.00134934322f);
        p = fmaf(p, w, -0.00367342844f);  p = fmaf(p, w, 0.00573950773f);
        p = fmaf(p, w, -0.0076224613f);   p = fmaf(p, w, 0.00943887047f);
        p = fmaf(p, w, 1.00167406f);      p = fmaf(p, w, 2.83297682f);
    }
    return p * x;
}

__device__ float bits_to_normal(unsigned b) {
    float f = __uint_as_float((b >> 9) | 0x3f800000u) - 1.0f;
    const float lo = -0.99999994f;
    float u = fmaxf(lo, f * 2.0f + lo);
    return 1.41421356f * erfinv_f32(u);
}

__global__ void probes_kernel() {
    int i = threadIdx.x;  // 1024 threads
    unsigned a, b;
    threefry2x32(0u, 101u, 0u, (unsigned)i, &a, &b);
    g_probe1[i] = bits_to_normal(a ^ b);
    threefry2x32(0u, 102u, 0u, (unsigned)i, &a, &b);
    g_probe2[i] = bits_to_normal(a ^ b);
}

// ---- fast_polar pieces ----
__global__ void gemv_sq_kernel(const float* __restrict__ U, const float* __restrict__ v) {
    int r = blockIdx.x;
    const float* u = U + (size_t)r * CC;
    float acc = 0.f;
    for (int c = threadIdx.x; c < CC; c += 256) acc += u[c] * v[c];
    #pragma unroll
    for (int o = 16; o > 0; o >>= 1) acc += __shfl_xor_sync(0xffffffffu, acc, o);
    __shared__ float sm[8];
    if ((threadIdx.x & 31) == 0) sm[threadIdx.x >> 5] = acc;
    __syncthreads();
    if (threadIdx.x == 0) {
        float t = 0.f;
        #pragma unroll
        for (int i = 0; i < 8; i++) t += sm[i];
        g_rowsq[r] = t * t;
    }
}

__global__ void reduce_ss_kernel() {
    __shared__ float sm[512];
    int t = threadIdx.x;
    sm[t] = g_rowsq[t] + g_rowsq[t + 512];
    __syncthreads();
    for (int s = 256; s > 0; s >>= 1) { if (t < s) sm[t] += sm[t + s]; __syncthreads(); }
    if (t == 0) g_ss = sqrtf(sm[0]) + 1e-8f;
}

__global__ void polar_update_kernel(const float* __restrict__ src, float* __restrict__ dst) {
    int idx = blockIdx.x * 256 + threadIdx.x;
    int i = idx >> 10, j = idx & (CC - 1);
    float s = g_ss;
    float diag = (i == j) ? 2.0f : 0.0f;
    dst[idx] = 0.5f * (src[idx] + (diag - src[(size_t)j * CC + i] / s) / s);
}

// ---- data movement ----
__global__ void init_head_kernel(const float* __restrict__ idn) {
    int b = blockIdx.x;
    for (int c = threadIdx.x; c < CC; c += 256) g_L[(size_t)b * 2048 * CC + c] = idn[c];
}

__global__ void copy_rows_kernel(const float* __restrict__ S, int sn, int soff, int sstr, int scnt,
                                 float* __restrict__ D, int dn, int doff, int dstr) {
    int r = blockIdx.x;
    int b = r / scnt, i = r % scnt;
    const float* s = S + ((size_t)b * sn + soff + (size_t)i * sstr) * CC;
    float* d = D + ((size_t)b * dn + doff + (size_t)i * dstr) * CC;
    for (int c = threadIdx.x; c < CC; c += 256) d[c] = s[c];
}

// fused upsweep copies for level l: S[l][0]=L[l][0] and S[l][2i+1]=S[l+1][i]
__global__ void up_copy_kernel(const float* __restrict__ Lbuf, int ofL,
                               const float* __restrict__ Snx, int ofnx, int nnx,
                               float* __restrict__ Sl, int ofS) {
    int r = blockIdx.x;
    int per = 1 + nnx;
    int b = r / per, i = r % per;
    const float* src;
    float* dst;
    if (i == 0) {
        src = Lbuf + ((size_t)b * 2048 + ofL) * CC;
        dst = Sl + ((size_t)b * 2048 + ofS) * CC;
    } else {
        src = Snx + ((size_t)b * 2048 + ofnx + (i - 1)) * CC;
        dst = Sl + ((size_t)b * 2048 + ofS + 1 + 2 * (i - 1)) * CC;
    }
    for (int c = threadIdx.x; c < CC; c += 256) dst[c] = src[c];
}

__global__ void mult_kernel() {
    int r = blockIdx.x;                 // 0..8191
    int b = r >> 10, t = r & 1023;
    const float* s = g_S + ((size_t)b * 2048 + 1 + t) * CC;
    const float* v = g_vbuf + (size_t)r * CC;
    float* a = g_Amul + (size_t)r * CC;
    for (int c = threadIdx.x; c < CC; c += 256) a[c] = s[c] * v[c];
}

// range_norm over sums of ks partials of Z, scatter via (off,stride) map
__global__ void rownorm_kernel(const float* __restrict__ Z, int ks, int Mrows,
                               float* __restrict__ Ob, int on, int ooff, int ostr, int ocnt) {
    int r = blockIdx.x;
    size_t stride = (size_t)Mrows * CC;
    size_t rbase = (size_t)r * CC;
    float vals[4];
    float mn = 1e30f, mx = -1e30f;
    #pragma unroll
    for (int i = 0; i < 4; i++) {
        int c = threadIdx.x + i * 256;
        float v = 0.f;
        for (int p = 0; p < ks; p++) v += Z[p * stride + rbase + c];
        vals[i] = v;
        mn = fminf(mn, v); mx = fmaxf(mx, v);
    }
    #pragma unroll
    for (int o = 16; o > 0; o >>= 1) {
        mn = fminf(mn, __shfl_xor_sync(0xffffffffu, mn, o));
        mx = fmaxf(mx, __shfl_xor_sync(0xffffffffu, mx, o));
    }
    __shared__ float smn[8], smx[8];
    int w = threadIdx.x >> 5, l = threadIdx.x & 31;
    if (l == 0) { smn[w] = mn; smx[w] = mx; }
    __syncthreads();
    if (threadIdx.x == 0) {
        float a = smn[0], b2 = smx[0];
        #pragma unroll
        for (int i = 1; i < 8; i++) { a = fminf(a, smn[i]); b2 = fmaxf(b2, smx[i]); }
        smn[0] = a; smx[0] = b2;
    }
    __syncthreads();
    mn = smn[0]; mx = smx[0];
    float inv = 2.0f / (mx - mn + 1e-8f);
    int b = r / ocnt, i2 = r % ocnt;
    float* o = Ob + ((size_t)b * on + ooff + (size_t)i2 * ostr) * CC;
    #pragma unroll
    for (int i = 0; i < 4; i++) {
        int c = threadIdx.x + i * 256;
        o[c] = (vals[i] - mn) * inv - 1.0f;
    }
}

// ---- host orchestration ----
static inline void tg(int M, int nkt, int ks,
                      const float* A1, int a1n, int a1o, int a1s, int a1c, const float* B1,
                      const float* A2, int a2n, int a2o, int a2s, int a2c, const float* B2,
                      float* O, int on, int oo, int os, int oc) {
    dim3 grid(8, (M + 127) / 128, ks);
    tgemm_kernel<<<grid, 256, TG_SMEM>>>(M, nkt, ks,
                                         A1, a1n, a1o, a1s, a1c, B1,
                                         A2, a2n, a2o, a2s, a2c, B2,
                                         O, on, oo, os, oc);
}

extern "C" void kernel_launch(void* const* d_in, const int* in_sizes, int n_in,
                              void* d_out, int out_size) {
    (void)in_sizes; (void)n_in; (void)out_size;
    const float* x   = (const float*)d_in[0];
    const float* Wq  = (const float*)d_in[1];
    const float* Wv  = (const float*)d_in[2];
    const float* Wc  = (const float*)d_in[3];
    const float* idn = (const float*)d_in[4];
    const float* P1  = (const float*)d_in[5];
    const float* P2  = (const float*)d_in[6];
    float* out = (float*)d_out;

    cudaFuncSetAttribute(tgemm_kernel, cudaFuncAttributeMaxDynamicSharedMemorySize, TG_SMEM);

    float *pL, *pS, *pV, *pA, *pZ, *pow1, *pow2, *pUt, *ppr1, *ppr2;
    cudaGetSymbolAddress((void**)&pL,   g_L);
    cudaGetSymbolAddress((void**)&pS,   g_S);
    cudaGetSymbolAddress((void**)&pV,   g_vbuf);
    cudaGetSymbolAddress((void**)&pA,   g_Amul);
    cudaGetSymbolAddress((void**)&pZ,   g_Z);
    cudaGetSymbolAddress((void**)&pow1, g_ow1);
    cudaGetSymbolAddress((void**)&pow2, g_ow2);
    cudaGetSymbolAddress((void**)&pUt,  g_Utmp);
    cudaGetSymbolAddress((void**)&ppr1, g_probe1);
    cudaGetSymbolAddress((void**)&ppr2, g_probe2);

    // 1) probes
    probes_kernel<<<1, 1024>>>();

    // 2) fast_polar(P1)->ow1, fast_polar(P2)->ow2 (2 iterations each, exact fp32)
    gemv_sq_kernel<<<CC, 256>>>(P1, ppr1);
    reduce_ss_kernel<<<1, 512>>>();
    polar_update_kernel<<<CC * CC / 256, 256>>>(P1, pUt);
    gemv_sq_kernel<<<CC, 256>>>(pUt, ppr1);
    reduce_ss_kernel<<<1, 512>>>();
    polar_update_kernel<<<CC * CC / 256, 256>>>(pUt, pow1);

    gemv_sq_kernel<<<CC, 256>>>(P2, ppr2);
    reduce_ss_kernel<<<1, 512>>>();
    polar_update_kernel<<<CC * CC / 256, 256>>>(P2, pUt);
    gemv_sq_kernel<<<CC, 256>>>(pUt, ppr2);
    reduce_ss_kernel<<<1, 512>>>();
    polar_update_kernel<<<CC * CC / 256, 256>>>(pUt, pow2);

    // 3) seq head + projections (B operand = W directly, [N,K] row-major)
    init_head_kernel<<<8, 256>>>(idn);
    tg(8192, 32, 1, x, 1024, 0, 1, 1024, Wq, x, 1024, 0, 1, 1024, Wq, pL, 2048, 1, 1, 1024);
    tg(8192, 32, 1, x, 1024, 0, 1, 1024, Wv, x, 1024, 0, 1, 1024, Wv, pV, 1024, 0, 1, 1024);

    // 4) scan tree (exact jax.lax.associative_scan recursion, iterative form)
    static const int NL = 11;
    static const int nlev[NL] = {1025, 512, 256, 128, 64, 32, 16, 8, 4, 2, 1};
    static const int olev[NL] = {0, 1025, 1537, 1793, 1921, 1985, 2017, 2033, 2041, 2045, 2047};

    // down: L[l+1][i] = combine(L[l][2i], L[l][2i+1])  (merged K=2048 GEMM)
    for (int l = 0; l < NL - 1; l++) {
        int cnt = nlev[l] / 2, M = 8 * cnt;
        int gy = (M + 127) / 128;
        int ks = 64 / gy; if (ks < 1) ks = 1;
        tg(M, 64, ks,
           pL, 2048, olev[l],     2, cnt, pow1,
           pL, 2048, olev[l] + 1, 2, cnt, pow2,
           pZ, cnt, 0, 1, cnt);
        rownorm_kernel<<<M, 256>>>(pZ, ks, M, pL, 2048, olev[l + 1], 1, cnt);
    }

    // up: S[10]=L[10]; S[l][0]=L[l][0], S[l][2i+1]=S[l+1][i],
    //     S[l][2i+2]=combine(S[l+1][i], L[l][2i+2])
    copy_rows_kernel<<<8, 256>>>(pL, 2048, olev[10], 1, 1, pS, 2048, olev[10], 1);
    for (int l = NL - 2; l >= 0; l--) {
        int ce = (nlev[l] - 1) / 2;
        up_copy_kernel<<<8 * (1 + nlev[l + 1]), 256>>>(pL, olev[l], pS, olev[l + 1], nlev[l + 1],
                                                       pS, olev[l]);
        if (ce > 0) {
            int M = 8 * ce;
            int gy = (M + 127) / 128;
            int ks = 64 / gy; if (ks < 1) ks = 1;
            tg(M, 64, ks,
               pS, 2048, olev[l + 1], 1, ce, pow1,
               pL, 2048, olev[l] + 2, 2, ce, pow2,
               pZ, ce, 0, 1, ce);
            rownorm_kernel<<<M, 256>>>(pZ, ks, M, pS, 2048, olev[l] + 2, 2, ce);
        }
    }

    // 5) Y = (scanned * v) @ Wc^T
    mult_kernel<<<8192, 256>>>();
    tg(8192, 32, 1, pA, 1024, 0, 1, 1024, Wc, pA, 1024, 0, 1, 1024, Wc, out, 1024, 0, 1, 1024);
}

// round 13
// speedup vs baseline: 1.3326x; 1.3326x over previous
#include <cuda_runtime.h>
#include <cstdint>

#define CC 1024

// ---- device scratch ----
__device__ float g_L[8 * 2048 * CC];
__device__ float g_S[8 * 2048 * CC];
__device__ float g_vbuf[8 * 1024 * CC];
__device__ float g_Amul[8 * 1024 * CC];
__device__ float g_Z[8192 * CC];
__device__ float g_ow1[CC * CC];
__device__ float g_ow2[CC * CC];
__device__ float g_Utmp[CC * CC];
__device__ float g_probe1[CC];
__device__ float g_probe2[CC];
__device__ float g_rowsq[CC];
__device__ float g_ss;

__device__ __forceinline__ uint32_t smem_to_u32(const void* p) {
    uint32_t a;
    asm("{ .reg .u64 t; cvta.to.shared.u64 t, %1; cvt.u32.u64 %0, t; }" : "=r"(a) : "l"(p));
    return a;
}

// hi = truncated-to-tf32; lo = exact remainder (low bits ignored by mma.tf32)
__device__ __forceinline__ void split1(uint32_t raw, uint32_t& h, uint32_t& l) {
    h = raw & 0xffffe000u;
    l = __float_as_uint(__uint_as_float(raw) - __uint_as_float(h));
}

__device__ __forceinline__ void mma8(float* c, const uint32_t* a, uint32_t b0, uint32_t b1) {
    asm volatile("mma.sync.aligned.m16n8k8.row.col.f32.tf32.tf32.f32 "
                 "{%0,%1,%2,%3}, {%4,%5,%6,%7}, {%8,%9}, {%0,%1,%2,%3};"
                 : "+f"(c[0]), "+f"(c[1]), "+f"(c[2]), "+f"(c[3])
                 : "r"(a[0]), "r"(a[1]), "r"(a[2]), "r"(a[3]), "r"(b0), "r"(b1));
}

__device__ __forceinline__ void cp16(uint32_t dst, const void* src) {
    asm volatile("cp.async.ca.shared.global [%0], [%1], 16;" :: "r"(dst), "l"(src));
}
#define CP_COMMIT() asm volatile("cp.async.commit_group;")
#define CP_WAIT1()  asm volatile("cp.async.wait_group 1;")
#define CP_WAIT0()  asm volatile("cp.async.wait_group 0;")

// SMEM: 2 stages x 32KB. Per stage (u32 idx):
//   A word (row,k) at ((row>>4)*4 + (k>>3))*128 + (((row>>3)&1) + 2*((k>>2)&1))*32 + (row&7)*4 + (k&3)
//   B word (n,k)  at 4096 + ((n>>3)*4 + (k>>3))*64 + ((k>>2)&1)*32 + (n&7)*4 + (k&3)
#define TG_SMEM 65536

// ---- tensor-core GEMM (3xTF32, cp.async double-buffered, dual-K) ----
// 128 threads, 4 warps in 2x2 grid, warp tile 64x64.
// D[M x 1024]; k-tiles 0..31 use (A1,B1), 32..63 use (A2,B2) when nkt=64.
// A/O rows via (base,n,off,stride,cnt) map. B rows are output dims [N,K].
// blockIdx.z = kz (split-K): k-tiles [kz*per, kz*per+per) -> partial at O + kz*M*1024.
__global__ __launch_bounds__(128, 2)
void tgemm_kernel(int M, int nkt, int ks,
                  const float* __restrict__ A1, int a1n, int a1off, int a1str, int a1cnt,
                  const float* __restrict__ B1,
                  const float* __restrict__ A2, int a2n, int a2off, int a2str, int a2cnt,
                  const float* __restrict__ B2,
                  float* __restrict__ O, int on, int ooff, int ostr, int ocnt) {
    extern __shared__ uint32_t sm[];
    const uint32_t smb = smem_to_u32(sm);
    const int tid = threadIdx.x;
    const int wid = tid >> 5, lane = tid & 31;
    const int wm = wid >> 1, wn = wid & 1;        // 2 x 2 warp grid
    const int g = lane >> 2, t4 = lane & 3;
    const int bn = blockIdx.x * 128, bm = blockIdx.y * 128;
    const int kz = blockIdx.z;

    const int rr = tid;                            // 0..127: one row of A and B per thread
    int gr = bm + rr; if (gr > M - 1) gr = M - 1;
    const float* ap1 = A1 + ((size_t)(gr / a1cnt) * a1n + a1off + (size_t)(gr % a1cnt) * a1str) * 1024;
    const float* ap2 = A2 + ((size_t)(gr / a2cnt) * a2n + a2off + (size_t)(gr % a2cnt) * a2str) * 1024;
    const float* bp1 = B1 + (size_t)(bn + rr) * 1024;
    const float* bp2 = B2 + (size_t)(bn + rr) * 1024;

    const uint32_t adst0 = ((rr >> 4) * 512 + ((rr >> 3) & 1) * 32 + (rr & 7) * 4) * 4u;
    const uint32_t bdst0 = (4096 + (rr >> 3) * 256 + (rr & 7) * 4) * 4u;

    float acc[4][8][4];
    #pragma unroll
    for (int i = 0; i < 4; i++)
        #pragma unroll
        for (int j = 0; j < 8; j++)
            #pragma unroll
            for (int q = 0; q < 4; q++) acc[i][j][q] = 0.f;

    const int per = nkt / ks;
    const int c0 = kz * per, c1 = c0 + per;

    auto issue = [&](int c) {
        const float* ap = (c >= 32) ? ap2 : ap1;
        const float* bp = (c >= 32) ? bp2 : bp1;
        int ko = (c & 31) * 32;
        uint32_t st = smb + (uint32_t)(c & 1) * 32768u;
        #pragma unroll
        for (int f = 0; f < 8; f++) {
            cp16(st + adst0 + (f >> 1) * 512u + (f & 1) * 256u, ap + ko + f * 4);
            cp16(st + bdst0 + (f >> 1) * 256u + (f & 1) * 128u, bp + ko + f * 4);
        }
        CP_COMMIT();
    };

    issue(c0);
    if (per > 1) issue(c0 + 1);

    for (int c = c0; c < c1; c++) {
        if (c + 1 < c1) { CP_WAIT1(); } else { CP_WAIT0(); }
        __syncthreads();
        const int st32 = (c & 1) * 8192;
        #pragma unroll
        for (int ks_ = 0; ks_ < 4; ks_++) {
            uint32_t bh[8][2], bl[8][2];
            #pragma unroll
            for (int nt = 0; nt < 8; nt++) {
                int bb = st32 + 4096 + ((wn * 8 + nt) * 4 + ks_) * 64 + lane;
                split1(sm[bb], bh[nt][0], bl[nt][0]);
                split1(sm[bb + 32], bh[nt][1], bl[nt][1]);
            }
            #pragma unroll
            for (int mt = 0; mt < 4; mt++) {
                uint32_t ah[4], al[4];
                int base = st32 + ((wm * 4 + mt) * 4 + ks_) * 128 + lane;
                #pragma unroll
                for (int r = 0; r < 4; r++) split1(sm[base + r * 32], ah[r], al[r]);
                #pragma unroll
                for (int nt = 0; nt < 8; nt++) {
                    mma8(acc[mt][nt], ah, bh[nt][0], bh[nt][1]);
                    mma8(acc[mt][nt], ah, bl[nt][0], bl[nt][1]);
                    mma8(acc[mt][nt], al, bh[nt][0], bh[nt][1]);
                }
            }
        }
        __syncthreads();
        if (c + 2 < c1) issue(c + 2);
    }

    O += (size_t)kz * M * 1024;

    #pragma unroll
    for (int mt = 0; mt < 4; mt++) {
        int r0 = bm + wm * 64 + mt * 16 + g;
        #pragma unroll
        for (int half = 0; half < 2; half++) {
            int r = r0 + half * 8;
            if (r < M) {
                float* orow = O + ((size_t)(r / ocnt) * on + ooff + (size_t)(r % ocnt) * ostr) * 1024
                              + bn + wn * 64;
                #pragma unroll
                for (int nt = 0; nt < 8; nt++) {
                    float2 v = half ? make_float2(acc[mt][nt][2], acc[mt][nt][3])
                                    : make_float2(acc[mt][nt][0], acc[mt][nt][1]);
                    *(float2*)(orow + nt * 8 + t4 * 2) = v;
                }
            }
        }
    }
}

// ---- threefry2x32 (exact JAX, partitionable layout) -> normal probes ----
__device__ __forceinline__ unsigned rotl32(unsigned x, int d) { return (x << d) | (x >> (32 - d)); }

__device__ void threefry2x32(unsigned k0, unsigned k1, unsigned x0, unsigned x1,
                             unsigned* o0, unsigned* o1) {
    unsigned ks[3] = {k0, k1, k0 ^ k1 ^ 0x1BD11BDAu};
    const int rot0[4] = {13, 15, 26, 6};
    const int rot1[4] = {17, 29, 16, 24};
    x0 += ks[0]; x1 += ks[1];
    #pragma unroll
    for (int g = 0; g < 5; g++) {
        if ((g & 1) == 0) {
            #pragma unroll
            for (int j = 0; j < 4; j++) { x0 += x1; x1 = rotl32(x1, rot0[j]); x1 ^= x0; }
        } else {
            #pragma unroll
            for (int j = 0; j < 4; j++) { x0 += x1; x1 = rotl32(x1, rot1[j]); x1 ^= x0; }
        }
        x0 += ks[(g + 1) % 3];
        x1 += ks[(g + 2) % 3] + (unsigned)(g + 1);
    }
    *o0 = x0; *o1 = x1;
}

__device__ float erfinv_f32(float x) {  // XLA ErfInv32 (Giles)
    float w = -log1pf(-x * x), p;
    if (w < 5.0f) {
        w -= 2.5f;
        p = 2.81022636e-08f;
        p = fmaf(p, w, 3.43273939e-07f);  p = fmaf(p, w, -3.5233877e-06f);
        p = fmaf(p, w, -4.39150654e-06f); p = fmaf(p, w, 0.00021858087f);
        p = fmaf(p, w, -0.00125372503f);  p = fmaf(p, w, -0.00417768164f);
        p = fmaf(p, w, 0.246640727f);     p = fmaf(p, w, 1.50140941f);
    } else {
        w = sqrtf(w) - 3.0f;
        p = -0.000200214257f;
        p = fmaf(p, w, 0.000100950558f);  p = fmaf(p, w, 0.00134934322f);
        p = fmaf(p, w, -0.00367342844f);  p = fmaf(p, w, 0.00573950773f);
        p = fmaf(p, w, -0.0076224613f);   p = fmaf(p, w, 0.00943887047f);
        p = fmaf(p, w, 1.00167406f);      p = fmaf(p, w, 2.83297682f);
    }
    return p * x;
}

__device__ float bits_to_normal(unsigned b) {
    float f = __uint_as_float((b >> 9) | 0x3f800000u) - 1.0f;
    const float lo = -0.99999994f;
    float u = fmaxf(lo, f * 2.0f + lo);
    return 1.41421356f * erfinv_f32(u);
}

__global__ void probes_kernel() {
    int i = threadIdx.x;  // 1024 threads
    unsigned a, b;
    threefry2x32(0u, 101u, 0u, (unsigned)i, &a, &b);
    g_probe1[i] = bits_to_normal(a ^ b);
    threefry2x32(0u, 102u, 0u, (unsigned)i, &a, &b);
    g_probe2[i] = bits_to_normal(a ^ b);
}

// ---- fast_polar pieces ----
__global__ void gemv_sq_kernel(const float* __restrict__ U, const float* __restrict__ v) {
    int r = blockIdx.x;
    const float* u = U + (size_t)r * CC;
    float acc = 0.f;
    for (int c = threadIdx.x; c < CC; c += 256) acc += u[c] * v[c];
    #pragma unroll
    for (int o = 16; o > 0; o >>= 1) acc += __shfl_xor_sync(0xffffffffu, acc, o);
    __shared__ float sm[8];
    if ((threadIdx.x & 31) == 0) sm[threadIdx.x >> 5] = acc;
    __syncthreads();
    if (threadIdx.x == 0) {
        float t = 0.f;
        #pragma unroll
        for (int i = 0; i < 8; i++) t += sm[i];
        g_rowsq[r] = t * t;
    }
}

__global__ void reduce_ss_kernel() {
    __shared__ float sm[512];
    int t = threadIdx.x;
    sm[t] = g_rowsq[t] + g_rowsq[t + 512];
    __syncthreads();
    for (int s = 256; s > 0; s >>= 1) { if (t < s) sm[t] += sm[t + s]; __syncthreads(); }
    if (t == 0) g_ss = sqrtf(sm[0]) + 1e-8f;
}

__global__ void polar_update_kernel(const float* __restrict__ src, float* __restrict__ dst) {
    int idx = blockIdx.x * 256 + threadIdx.x;
    int i = idx >> 10, j = idx & (CC - 1);
    float s = g_ss;
    float diag = (i == j) ? 2.0f : 0.0f;
    dst[idx] = 0.5f * (src[idx] + (diag - src[(size_t)j * CC + i] / s) / s);
}

// ---- data movement ----
__global__ void init_head_kernel(const float* __restrict__ idn) {
    int b = blockIdx.x;
    for (int c = threadIdx.x; c < CC; c += 256) g_L[(size_t)b * 2048 * CC + c] = idn[c];
}

__global__ void copy_rows_kernel(const float* __restrict__ S, int sn, int soff, int sstr, int scnt,
                                 float* __restrict__ D, int dn, int doff, int dstr) {
    int r = blockIdx.x;
    int b = r / scnt, i = r % scnt;
    const float* s = S + ((size_t)b * sn + soff + (size_t)i * sstr) * CC;
    float* d = D + ((size_t)b * dn + doff + (size_t)i * dstr) * CC;
    for (int c = threadIdx.x; c < CC; c += 256) d[c] = s[c];
}

// fused upsweep copies for level l: S[l][0]=L[l][0] and S[l][2i+1]=S[l+1][i]
__global__ void up_copy_kernel(const float* __restrict__ Lbuf, int ofL,
                               const float* __restrict__ Snx, int ofnx, int nnx,
                               float* __restrict__ Sl, int ofS) {
    int r = blockIdx.x;
    int per = 1 + nnx;
    int b = r / per, i = r % per;
    const float* src;
    float* dst;
    if (i == 0) {
        src = Lbuf + ((size_t)b * 2048 + ofL) * CC;
        dst = Sl + ((size_t)b * 2048 + ofS) * CC;
    } else {
        src = Snx + ((size_t)b * 2048 + ofnx + (i - 1)) * CC;
        dst = Sl + ((size_t)b * 2048 + ofS + 1 + 2 * (i - 1)) * CC;
    }
    for (int c = threadIdx.x; c < CC; c += 256) dst[c] = src[c];
}

__global__ void mult_kernel() {
    int r = blockIdx.x;                 // 0..8191
    int b = r >> 10, t = r & 1023;
    const float* s = g_S + ((size_t)b * 2048 + 1 + t) * CC;
    const float* v = g_vbuf + (size_t)r * CC;
    float* a = g_Amul + (size_t)r * CC;
    for (int c = threadIdx.x; c < CC; c += 256) a[c] = s[c] * v[c];
}

// range_norm over sums of ks partials of Z, scatter via (off,stride) map
__global__ void rownorm_kernel(const float* __restrict__ Z, int ks, int Mrows,
                               float* __restrict__ Ob, int on, int ooff, int ostr, int ocnt) {
    int r = blockIdx.x;
    size_t stride = (size_t)Mrows * CC;
    size_t rbase = (size_t)r * CC;
    float vals[4];
    float mn = 1e30f, mx = -1e30f;
    #pragma unroll
    for (int i = 0; i < 4; i++) {
        int c = threadIdx.x + i * 256;
        float v = 0.f;
        for (int p = 0; p < ks; p++) v += Z[p * stride + rbase + c];
        vals[i] = v;
        mn = fminf(mn, v); mx = fmaxf(mx, v);
    }
    #pragma unroll
    for (int o = 16; o > 0; o >>= 1) {
        mn = fminf(mn, __shfl_xor_sync(0xffffffffu, mn, o));
        mx = fmaxf(mx, __shfl_xor_sync(0xffffffffu, mx, o));
    }
    __shared__ float smn[8], smx[8];
    int w = threadIdx.x >> 5, l = threadIdx.x & 31;
    if (l == 0) { smn[w] = mn; smx[w] = mx; }
    __syncthreads();
    if (threadIdx.x == 0) {
        float a = smn[0], b2 = smx[0];
        #pragma unroll
        for (int i = 1; i < 8; i++) { a = fminf(a, smn[i]); b2 = fmaxf(b2, smx[i]); }
        smn[0] = a; smx[0] = b2;
    }
    __syncthreads();
    mn = smn[0]; mx = smx[0];
    float inv = 2.0f / (mx - mn + 1e-8f);
    int b = r / ocnt, i2 = r % ocnt;
    float* o = Ob + ((size_t)b * on + ooff + (size_t)i2 * ostr) * CC;
    #pragma unroll
    for (int i = 0; i < 4; i++) {
        int c = threadIdx.x + i * 256;
        o[c] = (vals[i] - mn) * inv - 1.0f;
    }
}

// ---- host orchestration ----
static inline void tg(int M, int nkt, int ks,
                      const float* A1, int a1n, int a1o, int a1s, int a1c, const float* B1,
                      const float* A2, int a2n, int a2o, int a2s, int a2c, const float* B2,
                      float* O, int on, int oo, int os, int oc) {
    dim3 grid(8, (M + 127) / 128, ks);
    tgemm_kernel<<<grid, 128, TG_SMEM>>>(M, nkt, ks,
                                         A1, a1n, a1o, a1s, a1c, B1,
                                         A2, a2n, a2o, a2s, a2c, B2,
                                         O, on, oo, os, oc);
}

extern "C" void kernel_launch(void* const* d_in, const int* in_sizes, int n_in,
                              void* d_out, int out_size) {
    (void)in_sizes; (void)n_in; (void)out_size;
    const float* x   = (const float*)d_in[0];
    const float* Wq  = (const float*)d_in[1];
    const float* Wv  = (const float*)d_in[2];
    const float* Wc  = (const float*)d_in[3];
    const float* idn = (const float*)d_in[4];
    const float* P1  = (const float*)d_in[5];
    const float* P2  = (const float*)d_in[6];
    float* out = (float*)d_out;

    cudaFuncSetAttribute(tgemm_kernel, cudaFuncAttributeMaxDynamicSharedMemorySize, TG_SMEM);

    float *pL, *pS, *pV, *pA, *pZ, *pow1, *pow2, *pUt, *ppr1, *ppr2;
    cudaGetSymbolAddress((void**)&pL,   g_L);
    cudaGetSymbolAddress((void**)&pS,   g_S);
    cudaGetSymbolAddress((void**)&pV,   g_vbuf);
    cudaGetSymbolAddress((void**)&pA,   g_Amul);
    cudaGetSymbolAddress((void**)&pZ,   g_Z);
    cudaGetSymbolAddress((void**)&pow1, g_ow1);
    cudaGetSymbolAddress((void**)&pow2, g_ow2);
    cudaGetSymbolAddress((void**)&pUt,  g_Utmp);
    cudaGetSymbolAddress((void**)&ppr1, g_probe1);
    cudaGetSymbolAddress((void**)&ppr2, g_probe2);

    // 1) probes
    probes_kernel<<<1, 1024>>>();

    // 2) fast_polar(P1)->ow1, fast_polar(P2)->ow2 (2 iterations each, exact fp32)
    gemv_sq_kernel<<<CC, 256>>>(P1, ppr1);
    reduce_ss_kernel<<<1, 512>>>();
    polar_update_kernel<<<CC * CC / 256, 256>>>(P1, pUt);
    gemv_sq_kernel<<<CC, 256>>>(pUt, ppr1);
    reduce_ss_kernel<<<1, 512>>>();
    polar_update_kernel<<<CC * CC / 256, 256>>>(pUt, pow1);

    gemv_sq_kernel<<<CC, 256>>>(P2, ppr2);
    reduce_ss_kernel<<<1, 512>>>();
    polar_update_kernel<<<CC * CC / 256, 256>>>(P2, pUt);
    gemv_sq_kernel<<<CC, 256>>>(pUt, ppr2);
    reduce_ss_kernel<<<1, 512>>>();
    polar_update_kernel<<<CC * CC / 256, 256>>>(pUt, pow2);

    // 3) seq head + projections (B operand = W directly, [N,K] row-major)
    init_head_kernel<<<8, 256>>>(idn);
    tg(8192, 32, 1, x, 1024, 0, 1, 1024, Wq, x, 1024, 0, 1, 1024, Wq, pL, 2048, 1, 1, 1024);
    tg(8192, 32, 1, x, 1024, 0, 1, 1024, Wv, x, 1024, 0, 1, 1024, Wv, pV, 1024, 0, 1, 1024);

    // 4) scan tree (exact jax.lax.associative_scan recursion, iterative form)
    static const int NL = 11;
    static const int nlev[NL] = {1025, 512, 256, 128, 64, 32, 16, 8, 4, 2, 1};
    static const int olev[NL] = {0, 1025, 1537, 1793, 1921, 1985, 2017, 2033, 2041, 2045, 2047};

    // down: L[l+1][i] = combine(L[l][2i], L[l][2i+1])  (merged K=2048 GEMM)
    for (int l = 0; l < NL - 1; l++) {
        int cnt = nlev[l] / 2, M = 8 * cnt;
        int gy = (M + 127) / 128;
        int ks = 64 / gy; if (ks < 1) ks = 1;
        tg(M, 64, ks,
           pL, 2048, olev[l],     2, cnt, pow1,
           pL, 2048, olev[l] + 1, 2, cnt, pow2,
           pZ, cnt, 0, 1, cnt);
        rownorm_kernel<<<M, 256>>>(pZ, ks, M, pL, 2048, olev[l + 1], 1, cnt);
    }

    // up: S[10]=L[10]; S[l][0]=L[l][0], S[l][2i+1]=S[l+1][i],
    //     S[l][2i+2]=combine(S[l+1][i], L[l][2i+2])
    copy_rows_kernel<<<8, 256>>>(pL, 2048, olev[10], 1, 1, pS, 2048, olev[10], 1);
    for (int l = NL - 2; l >= 0; l--) {
        int ce = (nlev[l] - 1) / 2;
        up_copy_kernel<<<8 * (1 + nlev[l + 1]), 256>>>(pL, olev[l], pS, olev[l + 1], nlev[l + 1],
                                                       pS, olev[l]);
        if (ce > 0) {
            int M = 8 * ce;
            int gy = (M + 127) / 128;
            int ks = 64 / gy; if (ks < 1) ks = 1;
            tg(M, 64, ks,
               pS, 2048, olev[l + 1], 1, ce, pow1,
               pL, 2048, olev[l] + 2, 2, ce, pow2,
               pZ, ce, 0, 1, ce);
            rownorm_kernel<<<M, 256>>>(pZ, ks, M, pS, 2048, olev[l] + 2, 2, ce);
        }
    }

    // 5) Y = (scanned * v) @ Wc^T
    mult_kernel<<<8192, 256>>>();
    tg(8192, 32, 1, pA, 1024, 0, 1, 1024, Wc, pA, 1024, 0, 1, 1024, Wc, out, 1024, 0, 1, 1024);
}

// round 14
// speedup vs baseline: 1.3354x; 1.0021x over previous
#include <cuda_runtime.h>
#include <cstdint>

#define CC 1024

// ---- device scratch ----
__device__ float g_L[8 * 2048 * CC];
__device__ float g_S[8 * 2048 * CC];
__device__ float g_vbuf[8 * 1024 * CC];
__device__ float g_Amul[8 * 1024 * CC];
__device__ float g_Z[8192 * CC];
__device__ float g_ow1[CC * CC];
__device__ float g_ow2[CC * CC];
__device__ float g_Utmp[CC * CC];
__device__ float g_probe1[CC];
__device__ float g_probe2[CC];
__device__ float g_rowsq[CC];
__device__ float g_ss;

__device__ __forceinline__ uint32_t smem_to_u32(const void* p) {
    uint32_t a;
    asm("{ .reg .u64 t; cvta.to.shared.u64 t, %1; cvt.u32.u64 %0, t; }" : "=r"(a) : "l"(p));
    return a;
}

// hi = truncated-to-tf32; lo = exact remainder (low bits ignored by mma.tf32)
__device__ __forceinline__ void split1(uint32_t raw, uint32_t& h, uint32_t& l) {
    h = raw & 0xffffe000u;
    l = __float_as_uint(__uint_as_float(raw) - __uint_as_float(h));
}

__device__ __forceinline__ void mma8(float* c, const uint32_t* a, uint32_t b0, uint32_t b1) {
    asm volatile("mma.sync.aligned.m16n8k8.row.col.f32.tf32.tf32.f32 "
                 "{%0,%1,%2,%3}, {%4,%5,%6,%7}, {%8,%9}, {%0,%1,%2,%3};"
                 : "+f"(c[0]), "+f"(c[1]), "+f"(c[2]), "+f"(c[3])
                 : "r"(a[0]), "r"(a[1]), "r"(a[2]), "r"(a[3]), "r"(b0), "r"(b1));
}

__device__ __forceinline__ void cp16(uint32_t dst, const void* src) {
    asm volatile("cp.async.ca.shared.global [%0], [%1], 16;" :: "r"(dst), "l"(src));
}
#define CP_COMMIT() asm volatile("cp.async.commit_group;")
#define CP_WAIT1()  asm volatile("cp.async.wait_group 1;")
#define CP_WAIT0()  asm volatile("cp.async.wait_group 0;")

// SMEM: 2 stages x 32KB. Per stage (u32 idx):
//   A word (row,k) at ((row>>4)*4 + (k>>3))*128 + (((row>>3)&1) + 2*((k>>2)&1))*32 + (row&7)*4 + (k&3)
//   B word (n,k)  at 4096 + ((n>>3)*4 + (k>>3))*64 + ((k>>2)&1)*32 + (n&7)*4 + (k&3)
#define TG_SMEM 65536

// ---- tensor-core GEMM (3xTF32, cp.async double-buffered, dual-K) ----
// 128 threads, 4 warps in 2x2 grid, warp tile 64x64.
// D[M x 1024]; k-tiles 0..31 use (A1,B1), 32..63 use (A2,B2) when nkt=64.
// A/O rows via (base,n,off,stride,cnt) map. B rows are output dims [N,K].
// blockIdx.z = kz (split-K): k-tiles [kz*per, kz*per+per) -> partial at O + kz*M*1024.
__global__ __launch_bounds__(128, 2)
void tgemm_kernel(int M, int nkt, int ks,
                  const float* __restrict__ A1, int a1n, int a1off, int a1str, int a1cnt,
                  const float* __restrict__ B1,
                  const float* __restrict__ A2, int a2n, int a2off, int a2str, int a2cnt,
                  const float* __restrict__ B2,
                  float* __restrict__ O, int on, int ooff, int ostr, int ocnt) {
    extern __shared__ uint32_t sm[];
    const uint32_t smb = smem_to_u32(sm);
    const int tid = threadIdx.x;
    const int wid = tid >> 5, lane = tid & 31;
    const int wm = wid >> 1, wn = wid & 1;        // 2 x 2 warp grid
    const int g = lane >> 2, t4 = lane & 3;
    const int bn = blockIdx.x * 128, bm = blockIdx.y * 128;
    const int kz = blockIdx.z;

    const int rr = tid;                            // 0..127: one row of A and B per thread
    int gr = bm + rr; if (gr > M - 1) gr = M - 1;
    const float* ap1 = A1 + ((size_t)(gr / a1cnt) * a1n + a1off + (size_t)(gr % a1cnt) * a1str) * 1024;
    const float* ap2 = A2 + ((size_t)(gr / a2cnt) * a2n + a2off + (size_t)(gr % a2cnt) * a2str) * 1024;
    const float* bp1 = B1 + (size_t)(bn + rr) * 1024;
    const float* bp2 = B2 + (size_t)(bn + rr) * 1024;

    const uint32_t adst0 = ((rr >> 4) * 512 + ((rr >> 3) & 1) * 32 + (rr & 7) * 4) * 4u;
    const uint32_t bdst0 = (4096 + (rr >> 3) * 256 + (rr & 7) * 4) * 4u;

    float acc[4][8][4];
    #pragma unroll
    for (int i = 0; i < 4; i++)
        #pragma unroll
        for (int j = 0; j < 8; j++)
            #pragma unroll
            for (int q = 0; q < 4; q++) acc[i][j][q] = 0.f;

    const int per = nkt / ks;
    const int c0 = kz * per, c1 = c0 + per;

    auto issue = [&](int c) {
        const float* ap = (c >= 32) ? ap2 : ap1;
        const float* bp = (c >= 32) ? bp2 : bp1;
        int ko = (c & 31) * 32;
        uint32_t st = smb + (uint32_t)(c & 1) * 32768u;
        #pragma unroll
        for (int f = 0; f < 8; f++) {
            cp16(st + adst0 + (f >> 1) * 512u + (f & 1) * 256u, ap + ko + f * 4);
            cp16(st + bdst0 + (f >> 1) * 256u + (f & 1) * 128u, bp + ko + f * 4);
        }
        CP_COMMIT();
    };

    issue(c0);
    if (per > 1) issue(c0 + 1);

    for (int c = c0; c < c1; c++) {
        if (c + 1 < c1) { CP_WAIT1(); } else { CP_WAIT0(); }
        __syncthreads();
        const int st32 = (c & 1) * 8192;
        #pragma unroll
        for (int ks_ = 0; ks_ < 4; ks_++) {
            uint32_t bh[8][2], bl[8][2];
            #pragma unroll
            for (int nt = 0; nt < 8; nt++) {
                int bb = st32 + 4096 + ((wn * 8 + nt) * 4 + ks_) * 64 + lane;
                split1(sm[bb], bh[nt][0], bl[nt][0]);
                split1(sm[bb + 32], bh[nt][1], bl[nt][1]);
            }
            #pragma unroll
            for (int mt = 0; mt < 4; mt++) {
                uint32_t ah[4], al[4];
                int base = st32 + ((wm * 4 + mt) * 4 + ks_) * 128 + lane;
                #pragma unroll
                for (int r = 0; r < 4; r++) split1(sm[base + r * 32], ah[r], al[r]);
                // product-major order: dependent mmas on the same accumulator are
                // 8 instructions apart -> no RAW stalls on the tensor pipe.
                #pragma unroll
                for (int nt = 0; nt < 8; nt++) mma8(acc[mt][nt], ah, bh[nt][0], bh[nt][1]);
                #pragma unroll
                for (int nt = 0; nt < 8; nt++) mma8(acc[mt][nt], ah, bl[nt][0], bl[nt][1]);
                #pragma unroll
                for (int nt = 0; nt < 8; nt++) mma8(acc[mt][nt], al, bh[nt][0], bh[nt][1]);
            }
        }
        __syncthreads();
        if (c + 2 < c1) issue(c + 2);
    }

    O += (size_t)kz * M * 1024;

    #pragma unroll
    for (int mt = 0; mt < 4; mt++) {
        int r0 = bm + wm * 64 + mt * 16 + g;
        #pragma unroll
        for (int half = 0; half < 2; half++) {
            int r = r0 + half * 8;
            if (r < M) {
                float* orow = O + ((size_t)(r / ocnt) * on + ooff + (size_t)(r % ocnt) * ostr) * 1024
                              + bn + wn * 64;
                #pragma unroll
                for (int nt = 0; nt < 8; nt++) {
                    float2 v = half ? make_float2(acc[mt][nt][2], acc[mt][nt][3])
                                    : make_float2(acc[mt][nt][0], acc[mt][nt][1]);
                    *(float2*)(orow + nt * 8 + t4 * 2) = v;
                }
            }
        }
    }
}

// ---- threefry2x32 (exact JAX, partitionable layout) -> normal probes ----
__device__ __forceinline__ unsigned rotl32(unsigned x, int d) { return (x << d) | (x >> (32 - d)); }

__device__ void threefry2x32(unsigned k0, unsigned k1, unsigned x0, unsigned x1,
                             unsigned* o0, unsigned* o1) {
    unsigned ks[3] = {k0, k1, k0 ^ k1 ^ 0x1BD11BDAu};
    const int rot0[4] = {13, 15, 26, 6};
    const int rot1[4] = {17, 29, 16, 24};
    x0 += ks[0]; x1 += ks[1];
    #pragma unroll
    for (int g = 0; g < 5; g++) {
        if ((g & 1) == 0) {
            #pragma unroll
            for (int j = 0; j < 4; j++) { x0 += x1; x1 = rotl32(x1, rot0[j]); x1 ^= x0; }
        } else {
            #pragma unroll
            for (int j = 0; j < 4; j++) { x0 += x1; x1 = rotl32(x1, rot1[j]); x1 ^= x0; }
        }
        x0 += ks[(g + 1) % 3];
        x1 += ks[(g + 2) % 3] + (unsigned)(g + 1);
    }
    *o0 = x0; *o1 = x1;
}

__device__ float erfinv_f32(float x) {  // XLA ErfInv32 (Giles)
    float w = -log1pf(-x * x), p;
    if (w < 5.0f) {
        w -= 2.5f;
        p = 2.81022636e-08f;
        p = fmaf(p, w, 3.43273939e-07f);  p = fmaf(p, w, -3.5233877e-06f);
        p = fmaf(p, w, -4.39150654e-06f); p = fmaf(p, w, 0.00021858087f);
        p = fmaf(p, w, -0.00125372503f);  p = fmaf(p, w, -0.00417768164f);
        p = fmaf(p, w, 0.246640727f);     p = fmaf(p, w, 1.50140941f);
    } else {
        w = sqrtf(w) - 3.0f;
        p = -0.000200214257f;
        p = fmaf(p, w, 0.000100950558f);  p = fmaf(p, w, 0.00134934322f);
        p = fmaf(p, w, -0.00367342844f);  p = fmaf(p, w, 0.00573950773f);
        p = fmaf(p, w, -0.0076224613f);   p = fmaf(p, w, 0.00943887047f);
        p = fmaf(p, w, 1.00167406f);      p = fmaf(p, w, 2.83297682f);
    }
    return p * x;
}

__device__ float bits_to_normal(unsigned b) {
    float f = __uint_as_float((b >> 9) | 0x3f800000u) - 1.0f;
    const float lo = -0.99999994f;
    float u = fmaxf(lo, f * 2.0f + lo);
    return 1.41421356f * erfinv_f32(u);
}

__global__ void probes_kernel() {
    int i = threadIdx.x;  // 1024 threads
    unsigned a, b;
    threefry2x32(0u, 101u, 0u, (unsigned)i, &a, &b);
    g_probe1[i] = bits_to_normal(a ^ b);
    threefry2x32(0u, 102u, 0u, (unsigned)i, &a, &b);
    g_probe2[i] = bits_to_normal(a ^ b);
}

// ---- fast_polar pieces ----
__global__ void gemv_sq_kernel(const float* __restrict__ U, const float* __restrict__ v) {
    int r = blockIdx.x;
    const float* u = U + (size_t)r * CC;
    float acc = 0.f;
    for (int c = threadIdx.x; c < CC; c += 256) acc += u[c] * v[c];
    #pragma unroll
    for (int o = 16; o > 0; o >>= 1) acc += __shfl_xor_sync(0xffffffffu, acc, o);
    __shared__ float sm[8];
    if ((threadIdx.x & 31) == 0) sm[threadIdx.x >> 5] = acc;
    __syncthreads();
    if (threadIdx.x == 0) {
        float t = 0.f;
        #pragma unroll
        for (int i = 0; i < 8; i++) t += sm[i];
        g_rowsq[r] = t * t;
    }
}

__global__ void reduce_ss_kernel() {
    __shared__ float sm[512];
    int t = threadIdx.x;
    sm[t] = g_rowsq[t] + g_rowsq[t + 512];
    __syncthreads();
    for (int s = 256; s > 0; s >>= 1) { if (t < s) sm[t] += sm[t + s]; __syncthreads(); }
    if (t == 0) g_ss = sqrtf(sm[0]) + 1e-8f;
}

__global__ void polar_update_kernel(const float* __restrict__ src, float* __restrict__ dst) {
    int idx = blockIdx.x * 256 + threadIdx.x;
    int i = idx >> 10, j = idx & (CC - 1);
    float s = g_ss;
    float diag = (i == j) ? 2.0f : 0.0f;
    dst[idx] = 0.5f * (src[idx] + (diag - src[(size_t)j * CC + i] / s) / s);
}

// ---- data movement ----
__global__ void init_head_kernel(const float* __restrict__ idn) {
    int b = blockIdx.x;
    for (int c = threadIdx.x; c < CC; c += 256) g_L[(size_t)b * 2048 * CC + c] = idn[c];
}

__global__ void copy_rows_kernel(const float* __restrict__ S, int sn, int soff, int sstr, int scnt,
                                 float* __restrict__ D, int dn, int doff, int dstr) {
    int r = blockIdx.x;
    int b = r / scnt, i = r % scnt;
    const float* s = S + ((size_t)b * sn + soff + (size_t)i * sstr) * CC;
    float* d = D + ((size_t)b * dn + doff + (size_t)i * dstr) * CC;
    for (int c = threadIdx.x; c < CC; c += 256) d[c] = s[c];
}

// fused upsweep copies for level l: S[l][0]=L[l][0] and S[l][2i+1]=S[l+1][i]
__global__ void up_copy_kernel(const float* __restrict__ Lbuf, int ofL,
                               const float* __restrict__ Snx, int ofnx, int nnx,
                               float* __restrict__ Sl, int ofS) {
    int r = blockIdx.x;
    int per = 1 + nnx;
    int b = r / per, i = r % per;
    const float* src;
    float* dst;
    if (i == 0) {
        src = Lbuf + ((size_t)b * 2048 + ofL) * CC;
        dst = Sl + ((size_t)b * 2048 + ofS) * CC;
    } else {
        src = Snx + ((size_t)b * 2048 + ofnx + (i - 1)) * CC;
        dst = Sl + ((size_t)b * 2048 + ofS + 1 + 2 * (i - 1)) * CC;
    }
    for (int c = threadIdx.x; c < CC; c += 256) dst[c] = src[c];
}

__global__ void mult_kernel() {
    int r = blockIdx.x;                 // 0..8191
    int b = r >> 10, t = r & 1023;
    const float* s = g_S + ((size_t)b * 2048 + 1 + t) * CC;
    const float* v = g_vbuf + (size_t)r * CC;
    float* a = g_Amul + (size_t)r * CC;
    for (int c = threadIdx.x; c < CC; c += 256) a[c] = s[c] * v[c];
}

// range_norm over sums of ks partials of Z, scatter via (off,stride) map
__global__ void rownorm_kernel(const float* __restrict__ Z, int ks, int Mrows,
                               float* __restrict__ Ob, int on, int ooff, int ostr, int ocnt) {
    int r = blockIdx.x;
    size_t stride = (size_t)Mrows * CC;
    size_t rbase = (size_t)r * CC;
    float vals[4];
    float mn = 1e30f, mx = -1e30f;
    #pragma unroll
    for (int i = 0; i < 4; i++) {
        int c = threadIdx.x + i * 256;
        float v = 0.f;
        for (int p = 0; p < ks; p++) v += Z[p * stride + rbase + c];
        vals[i] = v;
        mn = fminf(mn, v); mx = fmaxf(mx, v);
    }
    #pragma unroll
    for (int o = 16; o > 0; o >>= 1) {
        mn = fminf(mn, __shfl_xor_sync(0xffffffffu, mn, o));
        mx = fmaxf(mx, __shfl_xor_sync(0xffffffffu, mx, o));
    }
    __shared__ float smn[8], smx[8];
    int w = threadIdx.x >> 5, l = threadIdx.x & 31;
    if (l == 0) { smn[w] = mn; smx[w] = mx; }
    __syncthreads();
    if (threadIdx.x == 0) {
        float a = smn[0], b2 = smx[0];
        #pragma unroll
        for (int i = 1; i < 8; i++) { a = fminf(a, smn[i]); b2 = fmaxf(b2, smx[i]); }
        smn[0] = a; smx[0] = b2;
    }
    __syncthreads();
    mn = smn[0]; mx = smx[0];
    float inv = 2.0f / (mx - mn + 1e-8f);
    int b = r / ocnt, i2 = r % ocnt;
    float* o = Ob + ((size_t)b * on + ooff + (size_t)i2 * ostr) * CC;
    #pragma unroll
    for (int i = 0; i < 4; i++) {
        int c = threadIdx.x + i * 256;
        o[c] = (vals[i] - mn) * inv - 1.0f;
    }
}

// ---- host orchestration ----
static inline void tg(int M, int nkt, int ks,
                      const float* A1, int a1n, int a1o, int a1s, int a1c, const float* B1,
                      const float* A2, int a2n, int a2o, int a2s, int a2c, const float* B2,
                      float* O, int on, int oo, int os, int oc) {
    dim3 grid(8, (M + 127) / 128, ks);
    tgemm_kernel<<<grid, 128, TG_SMEM>>>(M, nkt, ks,
                                         A1, a1n, a1o, a1s, a1c, B1,
                                         A2, a2n, a2o, a2s, a2c, B2,
                                         O, on, oo, os, oc);
}

extern "C" void kernel_launch(void* const* d_in, const int* in_sizes, int n_in,
                              void* d_out, int out_size) {
    (void)in_sizes; (void)n_in; (void)out_size;
    const float* x   = (const float*)d_in[0];
    const float* Wq  = (const float*)d_in[1];
    const float* Wv  = (const float*)d_in[2];
    const float* Wc  = (const float*)d_in[3];
    const float* idn = (const float*)d_in[4];
    const float* P1  = (const float*)d_in[5];
    const float* P2  = (const float*)d_in[6];
    float* out = (float*)d_out;

    cudaFuncSetAttribute(tgemm_kernel, cudaFuncAttributeMaxDynamicSharedMemorySize, TG_SMEM);

    float *pL, *pS, *pV, *pA, *pZ, *pow1, *pow2, *pUt, *ppr1, *ppr2;
    cudaGetSymbolAddress((void**)&pL,   g_L);
    cudaGetSymbolAddress((void**)&pS,   g_S);
    cudaGetSymbolAddress((void**)&pV,   g_vbuf);
    cudaGetSymbolAddress((void**)&pA,   g_Amul);
    cudaGetSymbolAddress((void**)&pZ,   g_Z);
    cudaGetSymbolAddress((void**)&pow1, g_ow1);
    cudaGetSymbolAddress((void**)&pow2, g_ow2);
    cudaGetSymbolAddress((void**)&pUt,  g_Utmp);
    cudaGetSymbolAddress((void**)&ppr1, g_probe1);
    cudaGetSymbolAddress((void**)&ppr2, g_probe2);

    // 1) probes
    probes_kernel<<<1, 1024>>>();

    // 2) fast_polar(P1)->ow1, fast_polar(P2)->ow2 (2 iterations each, exact fp32)
    gemv_sq_kernel<<<CC, 256>>>(P1, ppr1);
    reduce_ss_kernel<<<1, 512>>>();
    polar_update_kernel<<<CC * CC / 256, 256>>>(P1, pUt);
    gemv_sq_kernel<<<CC, 256>>>(pUt, ppr1);
    reduce_ss_kernel<<<1, 512>>>();
    polar_update_kernel<<<CC * CC / 256, 256>>>(pUt, pow1);

    gemv_sq_kernel<<<CC, 256>>>(P2, ppr2);
    reduce_ss_kernel<<<1, 512>>>();
    polar_update_kernel<<<CC * CC / 256, 256>>>(P2, pUt);
    gemv_sq_kernel<<<CC, 256>>>(pUt, ppr2);
    reduce_ss_kernel<<<1, 512>>>();
    polar_update_kernel<<<CC * CC / 256, 256>>>(pUt, pow2);

    // 3) seq head + projections (B operand = W directly, [N,K] row-major)
    init_head_kernel<<<8, 256>>>(idn);
    tg(8192, 32, 1, x, 1024, 0, 1, 1024, Wq, x, 1024, 0, 1, 1024, Wq, pL, 2048, 1, 1, 1024);
    tg(8192, 32, 1, x, 1024, 0, 1, 1024, Wv, x, 1024, 0, 1, 1024, Wv, pV, 1024, 0, 1, 1024);

    // 4) scan tree (exact jax.lax.associative_scan recursion, iterative form)
    static const int NL = 11;
    static const int nlev[NL] = {1025, 512, 256, 128, 64, 32, 16, 8, 4, 2, 1};
    static const int olev[NL] = {0, 1025, 1537, 1793, 1921, 1985, 2017, 2033, 2041, 2045, 2047};

    // down: L[l+1][i] = combine(L[l][2i], L[l][2i+1])  (merged K=2048 GEMM)
    for (int l = 0; l < NL - 1; l++) {
        int cnt = nlev[l] / 2, M = 8 * cnt;
        int gy = (M + 127) / 128;
        int ks = 64 / gy; if (ks < 1) ks = 1;
        tg(M, 64, ks,
           pL, 2048, olev[l],     2, cnt, pow1,
           pL, 2048, olev[l] + 1, 2, cnt, pow2,
           pZ, cnt, 0, 1, cnt);
        rownorm_kernel<<<M, 256>>>(pZ, ks, M, pL, 2048, olev[l + 1], 1, cnt);
    }

    // up: S[10]=L[10]; S[l][0]=L[l][0], S[l][2i+1]=S[l+1][i],
    //     S[l][2i+2]=combine(S[l+1][i], L[l][2i+2])
    copy_rows_kernel<<<8, 256>>>(pL, 2048, olev[10], 1, 1, pS, 2048, olev[10], 1);
    for (int l = NL - 2; l >= 0; l--) {
        int ce = (nlev[l] - 1) / 2;
        up_copy_kernel<<<8 * (1 + nlev[l + 1]), 256>>>(pL, olev[l], pS, olev[l + 1], nlev[l + 1],
                                                       pS, olev[l]);
        if (ce > 0) {
            int M = 8 * ce;
            int gy = (M + 127) / 128;
            int ks = 64 / gy; if (ks < 1) ks = 1;
            tg(M, 64, ks,
               pS, 2048, olev[l + 1], 1, ce, pow1,
               pL, 2048, olev[l] + 2, 2, ce, pow2,
               pZ, ce, 0, 1, ce);
            rownorm_kernel<<<M, 256>>>(pZ, ks, M, pS, 2048, olev[l] + 2, 2, ce);
        }
    }

    // 5) Y = (scanned * v) @ Wc^T
    mult_kernel<<<8192, 256>>>();
    tg(8192, 32, 1, pA, 1024, 0, 1, 1024, Wc, pA, 1024, 0, 1, 1024, Wc, out, 1024, 0, 1, 1024);
}